// round 6
// baseline (speedup 1.0000x reference)
#include <cuda_runtime.h>

#define T_STEPS 20

typedef unsigned long long u64;

__device__ __forceinline__ u64 pack2(float x, float y) {
    u64 r; asm("mov.b64 %0, {%1, %2};" : "=l"(r) : "f"(x), "f"(y)); return r;
}
__device__ __forceinline__ void unpack2(u64 v, float& x, float& y) {
    asm("mov.b64 {%0, %1}, %2;" : "=f"(x), "=f"(y) : "l"(v));
}
// Packed fma: each half is an independent fma.rn.f32 -> bit-identical to scalar FFMA.
__device__ __forceinline__ u64 ffma2(u64 a, u64 b, u64 c) {
    u64 d; asm("fma.rn.f32x2 %0, %1, %2, %3;" : "=l"(d) : "l"(a), "l"(b), "l"(c)); return d;
}
__device__ __forceinline__ u64 fmul2(u64 a, u64 b) {
    u64 d; asm("mul.rn.f32x2 %0, %1, %2;" : "=l"(d) : "l"(a), "l"(b)); return d;
}
// FSET: float 1.0f/0.0f result of (a > b) in ONE instruction.
__device__ __forceinline__ float fset_gt(float a, float b) {
    float d; asm("set.gt.f32.f32 %0, %1, %2;" : "=f"(d) : "f"(a), "f"(b)); return d;
}

#define NPAIR 4   // 4 f32x2 pairs = 8 batch elems per thread

__global__ void __launch_bounds__(128) xornet_snn_kernel(
    const float4* __restrict__ x4,   // x [B,2]: one float4 = 2 batch elems
    const float*  __restrict__ w1,   // [4,2]
    const float*  __restrict__ w2,   // [1,4]
    float*        __restrict__ out,  // [T, B]
    int B)
{
    const int i  = blockIdx.x * blockDim.x + threadIdx.x;  // group of 8 batch elems
    const int b0 = i * (2 * NPAIR);
    if (b0 >= B) return;

    // 8 batch elems per thread: 4 float4 loads (independent -> MLP=4)
    float px0[2 * NPAIR], px1[2 * NPAIR];
#pragma unroll
    for (int p = 0; p < NPAIR; p++) {
        const float4 xa = x4[NPAIR * i + p];     // 2 batch elems
        px0[2 * p + 0] = xa.x; px1[2 * p + 0] = xa.y;
        px0[2 * p + 1] = xa.z; px1[2 * p + 1] = xa.w;
    }

    float w1v[4][2];
#pragma unroll
    for (int h = 0; h < 4; h++) {
        w1v[h][0] = __ldg(&w1[2 * h + 0]);
        w1v[h][1] = __ldg(&w1[2 * h + 1]);
    }
    u64 W2[4];
#pragma unroll
    for (int h = 0; h < 4; h++) {
        float w = __ldg(&w2[h]);
        W2[h] = pack2(w, w);
    }

    // cur[p][h]: same fma chain as before (bit-identical per lane).
    u64 cur[NPAIR][4];
#pragma unroll
    for (int p = 0; p < NPAIR; p++)
#pragma unroll
        for (int h = 0; h < 4; h++) {
            float c0 = fmaf(px1[2 * p + 0], w1v[h][1], px0[2 * p + 0] * w1v[h][0]);
            float c1 = fmaf(px1[2 * p + 1], w1v[h][1], px0[2 * p + 1] * w1v[h][0]);
            cur[p][h] = pack2(c0, c1);
        }

    const u64 BETA2 = pack2(0.9f, 0.9f);
    const u64 NEG1  = pack2(-1.0f, -1.0f);
    const u64 ZERO2 = pack2(0.0f, 0.0f);

    // Packed membranes + previous spikes (prev spike == this step's reset;
    // (m-1>0) <=> (m>1) exactly in fp32).
    u64 m1[NPAIR][4], s1[NPAIR][4], m2[NPAIR], s2[NPAIR];
#pragma unroll
    for (int p = 0; p < NPAIR; p++) {
#pragma unroll
        for (int h = 0; h < 4; h++) { m1[p][h] = ZERO2; s1[p][h] = ZERO2; }
        m2[p] = ZERO2; s2[p] = ZERO2;
    }

    float* outp = out + b0;

#pragma unroll 4
    for (int t = 0; t < T_STEPS; t++) {
        float so[NPAIR][2];
#pragma unroll
        for (int p = 0; p < NPAIR; p++) {   // 4 independent chains -> ILP
#pragma unroll
            for (int h = 0; h < 4; h++) {
                u64 m = ffma2(BETA2, m1[p][h], cur[p][h]);   // beta*m + cur
                m = ffma2(s1[p][h], NEG1, m);                // - s_prev (exact)
                m1[p][h] = m;
                float lo, hi; unpack2(m, lo, hi);
                s1[p][h] = pack2(fset_gt(lo, 1.0f), fset_gt(hi, 1.0f));
            }
            // o = spk1 . w2 (same h-order chain as scalar version)
            u64 o = fmul2(s1[p][0], W2[0]);
            o = ffma2(s1[p][1], W2[1], o);
            o = ffma2(s1[p][2], W2[2], o);
            o = ffma2(s1[p][3], W2[3], o);

            u64 m = ffma2(BETA2, m2[p], o);
            m = ffma2(s2[p], NEG1, m);
            m2[p] = m;
            float lo, hi; unpack2(m, lo, hi);
            so[p][0] = fset_gt(lo, 1.0f);
            so[p][1] = fset_gt(hi, 1.0f);
            s2[p] = pack2(so[p][0], so[p][1]);
        }
        // 8 contiguous floats: two STG.128
        reinterpret_cast<float4*>(outp)[0] =
            make_float4(so[0][0], so[0][1], so[1][0], so[1][1]);
        reinterpret_cast<float4*>(outp)[1] =
            make_float4(so[2][0], so[2][1], so[3][0], so[3][1]);
        outp += B;  // next timestep plane
    }
}

extern "C" void kernel_launch(void* const* d_in, const int* in_sizes, int n_in,
                              void* d_out, int out_size)
{
    const float* x  = (const float*)d_in[0];   // [B, 2]
    const float* w1 = (const float*)d_in[1];   // [4, 2]
    const float* w2 = (const float*)d_in[2];   // [1, 4]
    float* out      = (float*)d_out;           // [T, B, 1]

    const int B = in_sizes[0] / 2;
    const int nthreads = B / (2 * NPAIR);      // 8 batch elems per thread
    const int block = 128;
    const int grid = (nthreads + block - 1) / block;

    xornet_snn_kernel<<<grid, block>>>((const float4*)x, w1, w2, out, B);
}

// round 7
// speedup vs baseline: 1.4933x; 1.4933x over previous
#include <cuda_runtime.h>

#define T_STEPS 20

typedef unsigned long long u64;

__device__ __forceinline__ u64 pack2(float x, float y) {
    u64 r; asm("mov.b64 %0, {%1, %2};" : "=l"(r) : "f"(x), "f"(y)); return r;
}
__device__ __forceinline__ void unpack2(u64 v, float& x, float& y) {
    asm("mov.b64 {%0, %1}, %2;" : "=f"(x), "=f"(y) : "l"(v));
}
// Packed fma: each half is an independent fma.rn.f32 -> bit-identical to scalar FFMA.
__device__ __forceinline__ u64 ffma2(u64 a, u64 b, u64 c) {
    u64 d; asm("fma.rn.f32x2 %0, %1, %2, %3;" : "=l"(d) : "l"(a), "l"(b), "l"(c)); return d;
}
__device__ __forceinline__ u64 fmul2(u64 a, u64 b) {
    u64 d; asm("mul.rn.f32x2 %0, %1, %2;" : "=l"(d) : "l"(a), "l"(b)); return d;
}
// FSET: float 1.0f/0.0f result of (a > b) in ONE instruction.
__device__ __forceinline__ float fset_gt(float a, float b) {
    float d; asm("set.gt.f32.f32 %0, %1, %2;" : "=f"(d) : "f"(a), "f"(b)); return d;
}

__global__ void __launch_bounds__(256) xornet_snn_kernel(
    const float4* __restrict__ x4,   // x [B,2] as float4 pairs
    const float*  __restrict__ w1,   // [4,2]
    const float*  __restrict__ w2,   // [1,4]
    float*        __restrict__ out,  // [T, B]
    int B)
{
    const int i  = blockIdx.x * blockDim.x + threadIdx.x;  // group of 4 batch elems
    const int b0 = i * 4;
    if (b0 >= B) return;

    const float4 xa = x4[2 * i + 0];  // b0:{x0,x1}, b1:{x0,x1}
    const float4 xb = x4[2 * i + 1];  // b2:{x0,x1}, b3:{x0,x1}
    const float px0[4] = {xa.x, xa.z, xb.x, xb.z};
    const float px1[4] = {xa.y, xa.w, xb.y, xb.w};

    float w1v[4][2];
#pragma unroll
    for (int h = 0; h < 4; h++) {
        w1v[h][0] = __ldg(&w1[2 * h + 0]);
        w1v[h][1] = __ldg(&w1[2 * h + 1]);
    }
    u64 W2[4];
#pragma unroll
    for (int h = 0; h < 4; h++) {
        float w = __ldg(&w2[h]);
        W2[h] = pack2(w, w);
    }

    // cur[l][h]: same fma chain as before (bit-identical per lane).
    float cur[4][4];
#pragma unroll
    for (int l = 0; l < 4; l++)
#pragma unroll
        for (int h = 0; h < 4; h++)
            cur[l][h] = fmaf(px1[l], w1v[h][1], px0[l] * w1v[h][0]);

    const u64 BETA2 = pack2(0.9f, 0.9f);
    const u64 NEG1  = pack2(-1.0f, -1.0f);
    const u64 ZERO2 = pack2(0.0f, 0.0f);

    // Hidden layer state as SCALARS: the beta-fma and reset-fma use the
    // FFMA-imm form (rt=1) instead of packed ffma2 (rt=3, RF-bank bound).
    // Values are bit-identical: same fma.rn per lane.
    float m1[4][4], s1f[4][4];
#pragma unroll
    for (int l = 0; l < 4; l++)
#pragma unroll
        for (int h = 0; h < 4; h++) { m1[l][h] = 0.0f; s1f[l][h] = 0.0f; }

    // Second neuron stays packed (w2 is runtime -> no imm form available).
    u64 m2[2] = {ZERO2, ZERO2};
    u64 s2[2] = {ZERO2, ZERO2};

    float* outp = out + b0;

#pragma unroll 4
    for (int t = 0; t < T_STEPS; t++) {
        float so[2][2];
#pragma unroll
        for (int p = 0; p < 2; p++) {
            const int l0 = 2 * p, l1 = 2 * p + 1;
            u64 sp[4];
#pragma unroll
            for (int h = 0; h < 4; h++) {
                // m = m*0.9 + cur  (FFMA-imm, rt=1), then m = s*(-1) + m (FFMA-imm)
                float a = fmaf(m1[l0][h], 0.9f, cur[l0][h]);
                a = fmaf(s1f[l0][h], -1.0f, a);
                m1[l0][h] = a;
                float b = fmaf(m1[l1][h], 0.9f, cur[l1][h]);
                b = fmaf(s1f[l1][h], -1.0f, b);
                m1[l1][h] = b;
                float sa = fset_gt(a, 1.0f);
                float sb = fset_gt(b, 1.0f);
                s1f[l0][h] = sa;
                s1f[l1][h] = sb;
                sp[h] = pack2(sa, sb);       // pair for the packed dot
            }
            // o = spk1 . w2 : packed chain, same h-order & values as scalar chain
            u64 o = fmul2(sp[0], W2[0]);
            o = ffma2(sp[1], W2[1], o);
            o = ffma2(sp[2], W2[2], o);
            o = ffma2(sp[3], W2[3], o);

            u64 m = ffma2(BETA2, m2[p], o);  // 0.9*m2 + o
            m = ffma2(s2[p], NEG1, m);       // - s2_prev (exact)
            m2[p] = m;
            float lo, hi; unpack2(m, lo, hi);
            so[p][0] = fset_gt(lo, 1.0f);
            so[p][1] = fset_gt(hi, 1.0f);
            s2[p] = pack2(so[p][0], so[p][1]);
        }
        *reinterpret_cast<float4*>(outp) =
            make_float4(so[0][0], so[0][1], so[1][0], so[1][1]);
        outp += B;  // next timestep plane
    }
}

extern "C" void kernel_launch(void* const* d_in, const int* in_sizes, int n_in,
                              void* d_out, int out_size)
{
    const float* x  = (const float*)d_in[0];   // [B, 2]
    const float* w1 = (const float*)d_in[1];   // [4, 2]
    const float* w2 = (const float*)d_in[2];   // [1, 4]
    float* out      = (float*)d_out;           // [T, B, 1]

    const int B = in_sizes[0] / 2;
    const int nthreads = B / 4;                // 4 batch elems per thread
    const int block = 256;
    const int grid = (nthreads + block - 1) / block;

    xornet_snn_kernel<<<grid, block>>>((const float4*)x, w1, w2, out, B);
}

// round 8
// speedup vs baseline: 1.4958x; 1.0017x over previous
#include <cuda_runtime.h>

#define T_STEPS 20

typedef unsigned long long u64;

__device__ __forceinline__ u64 pack2(float x, float y) {
    u64 r; asm("mov.b64 %0, {%1, %2};" : "=l"(r) : "f"(x), "f"(y)); return r;
}
__device__ __forceinline__ void unpack2(u64 v, float& x, float& y) {
    asm("mov.b64 {%0, %1}, %2;" : "=f"(x), "=f"(y) : "l"(v));
}
// Packed fma: each half is an independent fma.rn.f32 -> bit-identical to scalar FFMA.
__device__ __forceinline__ u64 ffma2(u64 a, u64 b, u64 c) {
    u64 d; asm("fma.rn.f32x2 %0, %1, %2, %3;" : "=l"(d) : "l"(a), "l"(b), "l"(c)); return d;
}
__device__ __forceinline__ u64 fmul2(u64 a, u64 b) {
    u64 d; asm("mul.rn.f32x2 %0, %1, %2;" : "=l"(d) : "l"(a), "l"(b)); return d;
}
// FSET: float 1.0f/0.0f result of (a > b) in ONE instruction.
__device__ __forceinline__ float fset_gt(float a, float b) {
    float d; asm("set.gt.f32.f32 %0, %1, %2;" : "=f"(d) : "f"(a), "f"(b)); return d;
}

__global__ void __launch_bounds__(64) xornet_snn_kernel(
    const float4* __restrict__ x4,   // x [B,2] as float4 pairs
    const float*  __restrict__ w1,   // [4,2]
    const float*  __restrict__ w2,   // [1,4]
    float*        __restrict__ out,  // [T, B]
    int B)
{
    const int i  = blockIdx.x * blockDim.x + threadIdx.x;  // group of 4 batch elems
    const int b0 = i * 4;
    if (b0 >= B) return;

    const float4 xa = x4[2 * i + 0];  // b0:{x0,x1}, b1:{x0,x1}
    const float4 xb = x4[2 * i + 1];  // b2:{x0,x1}, b3:{x0,x1}
    const float px0[4] = {xa.x, xa.z, xb.x, xb.z};
    const float px1[4] = {xa.y, xa.w, xb.y, xb.w};

    float w1v[4][2];
#pragma unroll
    for (int h = 0; h < 4; h++) {
        w1v[h][0] = __ldg(&w1[2 * h + 0]);
        w1v[h][1] = __ldg(&w1[2 * h + 1]);
    }
    u64 W2[4];
#pragma unroll
    for (int h = 0; h < 4; h++) {
        float w = __ldg(&w2[h]);
        W2[h] = pack2(w, w);
    }

    // cur[p][h]: packed pair of lanes (2p, 2p+1); same fma chain as R1 (bit-identical).
    u64 cur[2][4];
#pragma unroll
    for (int p = 0; p < 2; p++)
#pragma unroll
        for (int h = 0; h < 4; h++) {
            float c0 = fmaf(px1[2 * p + 0], w1v[h][1], px0[2 * p + 0] * w1v[h][0]);
            float c1 = fmaf(px1[2 * p + 1], w1v[h][1], px0[2 * p + 1] * w1v[h][0]);
            cur[p][h] = pack2(c0, c1);
        }

    const u64 BETA2 = pack2(0.9f, 0.9f);
    const u64 NEG1  = pack2(-1.0f, -1.0f);
    const u64 ZERO2 = pack2(0.0f, 0.0f);

    // Packed membranes + previous spikes (prev spike == this step's reset;
    // (m-1>0) <=> (m>1) exactly in fp32).
    u64 m1[2][4], s1[2][4], m2[2], s2[2];
#pragma unroll
    for (int p = 0; p < 2; p++) {
#pragma unroll
        for (int h = 0; h < 4; h++) { m1[p][h] = ZERO2; s1[p][h] = ZERO2; }
        m2[p] = ZERO2; s2[p] = ZERO2;
    }

    float* outp = out + b0;

#pragma unroll 4
    for (int t = 0; t < T_STEPS; t++) {
        float so[2][2];  // output spikes for the 4 lanes this step
#pragma unroll
        for (int p = 0; p < 2; p++) {
#pragma unroll
            for (int h = 0; h < 4; h++) {
                // m = beta*m + cur  (packed fma, bit-identical halves)
                u64 m = ffma2(BETA2, m1[p][h], cur[p][h]);
                // m -= s_prev : fma(s,-1,m) == m-1 (single rounding, same as FADD) or m exactly
                m = ffma2(s1[p][h], NEG1, m);
                m1[p][h] = m;
                float lo, hi; unpack2(m, lo, hi);
                s1[p][h] = pack2(fset_gt(lo, 1.0f), fset_gt(hi, 1.0f));
            }
            // o = spk1 . w2 : packed mul + fma chain, same h-order & values as scalar chain
            u64 o = fmul2(s1[p][0], W2[0]);
            o = ffma2(s1[p][1], W2[1], o);
            o = ffma2(s1[p][2], W2[2], o);
            o = ffma2(s1[p][3], W2[3], o);

            u64 m = ffma2(BETA2, m2[p], o);
            m = ffma2(s2[p], NEG1, m);
            m2[p] = m;
            float lo, hi; unpack2(m, lo, hi);
            so[p][0] = fset_gt(lo, 1.0f);
            so[p][1] = fset_gt(hi, 1.0f);
            s2[p] = pack2(so[p][0], so[p][1]);
        }
        *reinterpret_cast<float4*>(outp) =
            make_float4(so[0][0], so[0][1], so[1][0], so[1][1]);
        outp += B;  // next timestep plane
    }
}

extern "C" void kernel_launch(void* const* d_in, const int* in_sizes, int n_in,
                              void* d_out, int out_size)
{
    const float* x  = (const float*)d_in[0];   // [B, 2]
    const float* w1 = (const float*)d_in[1];   // [4, 2]
    const float* w2 = (const float*)d_in[2];   // [1, 4]
    float* out      = (float*)d_out;           // [T, B, 1]

    const int B = in_sizes[0] / 2;
    const int nthreads = B / 4;                // 4 batch elems per thread
    const int block = 64;                      // small blocks -> fine-grained tail,
    const int grid = (nthreads + block - 1) / block;  // ~14 resident blocks/SM

    xornet_snn_kernel<<<grid, block>>>((const float4*)x, w1, w2, out, B);
}

// round 9
// speedup vs baseline: 1.6938x; 1.1323x over previous
#include <cuda_runtime.h>

#define T_STEPS 20

typedef unsigned long long u64;

// Compiler-visible pack/unpack: plain register-pair aliasing, no forced MOVs.
union f2u {
    u64 v;
    float2 f;
};
__device__ __forceinline__ u64 pack2(float x, float y) {
    f2u t; t.f.x = x; t.f.y = y; return t.v;
}
__device__ __forceinline__ void unpack2(u64 v, float& x, float& y) {
    f2u t; t.v = v; x = t.f.x; y = t.f.y;
}
// Packed fma: each half independent fma.rn.f32 -> bit-identical to scalar FFMA.
__device__ __forceinline__ u64 ffma2(u64 a, u64 b, u64 c) {
    u64 d; asm("fma.rn.f32x2 %0, %1, %2, %3;" : "=l"(d) : "l"(a), "l"(b), "l"(c)); return d;
}
__device__ __forceinline__ u64 fmul2(u64 a, u64 b) {
    u64 d; asm("mul.rn.f32x2 %0, %1, %2;" : "=l"(d) : "l"(a), "l"(b)); return d;
}
// Packed subtract: round(a-b) == fma(b,-1,a) value-for-value, but 2 operands (rt=2).
__device__ __forceinline__ u64 fsub2(u64 a, u64 b) {
    u64 d; asm("sub.rn.f32x2 %0, %1, %2;" : "=l"(d) : "l"(a), "l"(b)); return d;
}
// FSET: float 1.0f/0.0f result of (a > b) in ONE instruction.
__device__ __forceinline__ float fset_gt(float a, float b) {
    float d; asm("set.gt.f32.f32 %0, %1, %2;" : "=f"(d) : "f"(a), "f"(b)); return d;
}

__global__ void __launch_bounds__(256) xornet_snn_kernel(
    const float4* __restrict__ x4,   // x [B,2] as float4 pairs
    const float*  __restrict__ w1,   // [4,2]
    const float*  __restrict__ w2,   // [1,4]
    float*        __restrict__ out,  // [T, B]
    int B)
{
    const int i  = blockIdx.x * blockDim.x + threadIdx.x;  // group of 4 batch elems
    const int b0 = i * 4;
    if (b0 >= B) return;

    const float4 xa = x4[2 * i + 0];  // b0:{x0,x1}, b1:{x0,x1}
    const float4 xb = x4[2 * i + 1];  // b2:{x0,x1}, b3:{x0,x1}
    const float px0[4] = {xa.x, xa.z, xb.x, xb.z};
    const float px1[4] = {xa.y, xa.w, xb.y, xb.w};

    float w1v[4][2];
#pragma unroll
    for (int h = 0; h < 4; h++) {
        w1v[h][0] = __ldg(&w1[2 * h + 0]);
        w1v[h][1] = __ldg(&w1[2 * h + 1]);
    }
    u64 W2[4];
#pragma unroll
    for (int h = 0; h < 4; h++) {
        float w = __ldg(&w2[h]);
        W2[h] = pack2(w, w);
    }

    // cur[p][h]: packed pair of lanes (2p, 2p+1); same fma chain as before (bit-identical).
    u64 cur[2][4];
#pragma unroll
    for (int p = 0; p < 2; p++)
#pragma unroll
        for (int h = 0; h < 4; h++) {
            float c0 = fmaf(px1[2 * p + 0], w1v[h][1], px0[2 * p + 0] * w1v[h][0]);
            float c1 = fmaf(px1[2 * p + 1], w1v[h][1], px0[2 * p + 1] * w1v[h][0]);
            cur[p][h] = pack2(c0, c1);
        }

    const u64 BETA2 = pack2(0.9f, 0.9f);
    const u64 ZERO2 = pack2(0.0f, 0.0f);

    // Packed membranes + previous spikes (prev spike == this step's reset;
    // (m-1>0) <=> (m>1) exactly in fp32).
    u64 m1[2][4], s1[2][4], m2[2], s2[2];
#pragma unroll
    for (int p = 0; p < 2; p++) {
#pragma unroll
        for (int h = 0; h < 4; h++) { m1[p][h] = ZERO2; s1[p][h] = ZERO2; }
        m2[p] = ZERO2; s2[p] = ZERO2;
    }

    float* outp = out + b0;

#pragma unroll 4
    for (int t = 0; t < T_STEPS; t++) {
        float so[2][2];  // output spikes for the 4 lanes this step
#pragma unroll
        for (int p = 0; p < 2; p++) {
#pragma unroll
            for (int h = 0; h < 4; h++) {
                // m = beta*m + cur  (packed fma, bit-identical halves)
                u64 m = ffma2(BETA2, m1[p][h], cur[p][h]);
                // m -= s_prev : sub.rn == fma(s,-1,m) value-identical, rt=2
                m = fsub2(m, s1[p][h]);
                m1[p][h] = m;
                float lo, hi; unpack2(m, lo, hi);
                s1[p][h] = pack2(fset_gt(lo, 1.0f), fset_gt(hi, 1.0f));
            }
            // o = spk1 . w2 : packed mul + fma chain, same h-order & values as scalar chain
            u64 o = fmul2(s1[p][0], W2[0]);
            o = ffma2(s1[p][1], W2[1], o);
            o = ffma2(s1[p][2], W2[2], o);
            o = ffma2(s1[p][3], W2[3], o);

            u64 m = ffma2(BETA2, m2[p], o);
            m = fsub2(m, s2[p]);
            m2[p] = m;
            float lo, hi; unpack2(m, lo, hi);
            so[p][0] = fset_gt(lo, 1.0f);
            so[p][1] = fset_gt(hi, 1.0f);
            s2[p] = pack2(so[p][0], so[p][1]);
        }
        *reinterpret_cast<float4*>(outp) =
            make_float4(so[0][0], so[0][1], so[1][0], so[1][1]);
        outp += B;  // next timestep plane
    }
}

extern "C" void kernel_launch(void* const* d_in, const int* in_sizes, int n_in,
                              void* d_out, int out_size)
{
    const float* x  = (const float*)d_in[0];   // [B, 2]
    const float* w1 = (const float*)d_in[1];   // [4, 2]
    const float* w2 = (const float*)d_in[2];   // [1, 4]
    float* out      = (float*)d_out;           // [T, B, 1]

    const int B = in_sizes[0] / 2;
    const int nthreads = B / 4;                // 4 batch elems per thread
    const int block = 256;
    const int grid = (nthreads + block - 1) / block;

    xornet_snn_kernel<<<grid, block>>>((const float4*)x, w1, w2, out, B);
}

// round 10
// speedup vs baseline: 1.7002x; 1.0038x over previous
#include <cuda_runtime.h>

#define T_STEPS 20

typedef unsigned long long u64;

// Compiler-visible pack/unpack: plain register-pair aliasing, no forced MOVs.
union f2u {
    u64 v;
    float2 f;
};
__device__ __forceinline__ u64 pack2(float x, float y) {
    f2u t; t.f.x = x; t.f.y = y; return t.v;
}
__device__ __forceinline__ void unpack2(u64 v, float& x, float& y) {
    f2u t; t.v = v; x = t.f.x; y = t.f.y;
}
// Packed fma: each half independent fma.rn.f32 -> bit-identical to scalar FFMA.
__device__ __forceinline__ u64 ffma2(u64 a, u64 b, u64 c) {
    u64 d; asm("fma.rn.f32x2 %0, %1, %2, %3;" : "=l"(d) : "l"(a), "l"(b), "l"(c)); return d;
}
__device__ __forceinline__ u64 fmul2(u64 a, u64 b) {
    u64 d; asm("mul.rn.f32x2 %0, %1, %2;" : "=l"(d) : "l"(a), "l"(b)); return d;
}
// Packed subtract: round(a-b) == fma(b,-1,a) value-for-value (rt=2).
__device__ __forceinline__ u64 fsub2(u64 a, u64 b) {
    u64 d; asm("sub.rn.f32x2 %0, %1, %2;" : "=l"(d) : "l"(a), "l"(b)); return d;
}
// FSET: float 1.0f/0.0f result of (a > b) in ONE instruction.
__device__ __forceinline__ float fset_gt(float a, float b) {
    float d; asm("set.gt.f32.f32 %0, %1, %2;" : "=f"(d) : "f"(a), "f"(b)); return d;
}
// Streaming (evict-first) 128-bit store: output has zero reuse; keep L2 clean
// so steady-state writeback doesn't jam subsequent iterations.
__device__ __forceinline__ void stg_cs128(float* p, float a, float b, float c, float d) {
    asm volatile("st.global.cs.v4.f32 [%0], {%1, %2, %3, %4};"
                 :: "l"(p), "f"(a), "f"(b), "f"(c), "f"(d) : "memory");
}
// Streaming 128-bit load (x has zero reuse).
__device__ __forceinline__ float4 ldg_cs128(const float4* p) {
    float4 r;
    asm volatile("ld.global.nc.cs.v4.f32 {%0, %1, %2, %3}, [%4];"
                 : "=f"(r.x), "=f"(r.y), "=f"(r.z), "=f"(r.w) : "l"(p));
    return r;
}

__global__ void __launch_bounds__(256) xornet_snn_kernel(
    const float4* __restrict__ x4,   // x [B,2] as float4 pairs
    const float*  __restrict__ w1,   // [4,2]
    const float*  __restrict__ w2,   // [1,4]
    float*        __restrict__ out,  // [T, B]
    int B)
{
    const int i  = blockIdx.x * blockDim.x + threadIdx.x;  // group of 4 batch elems
    const int b0 = i * 4;
    if (b0 >= B) return;

    const float4 xa = ldg_cs128(&x4[2 * i + 0]);  // b0:{x0,x1}, b1:{x0,x1}
    const float4 xb = ldg_cs128(&x4[2 * i + 1]);  // b2:{x0,x1}, b3:{x0,x1}
    const float px0[4] = {xa.x, xa.z, xb.x, xb.z};
    const float px1[4] = {xa.y, xa.w, xb.y, xb.w};

    float w1v[4][2];
#pragma unroll
    for (int h = 0; h < 4; h++) {
        w1v[h][0] = __ldg(&w1[2 * h + 0]);
        w1v[h][1] = __ldg(&w1[2 * h + 1]);
    }
    u64 W2[4];
#pragma unroll
    for (int h = 0; h < 4; h++) {
        float w = __ldg(&w2[h]);
        W2[h] = pack2(w, w);
    }

    // cur[p][h]: packed pair of lanes (2p, 2p+1); same fma chain as before (bit-identical).
    u64 cur[2][4];
#pragma unroll
    for (int p = 0; p < 2; p++)
#pragma unroll
        for (int h = 0; h < 4; h++) {
            float c0 = fmaf(px1[2 * p + 0], w1v[h][1], px0[2 * p + 0] * w1v[h][0]);
            float c1 = fmaf(px1[2 * p + 1], w1v[h][1], px0[2 * p + 1] * w1v[h][0]);
            cur[p][h] = pack2(c0, c1);
        }

    const u64 BETA2 = pack2(0.9f, 0.9f);
    const u64 ZERO2 = pack2(0.0f, 0.0f);

    // Packed membranes + previous spikes (prev spike == this step's reset;
    // (m-1>0) <=> (m>1) exactly in fp32).
    u64 m1[2][4], s1[2][4], m2[2], s2[2];
#pragma unroll
    for (int p = 0; p < 2; p++) {
#pragma unroll
        for (int h = 0; h < 4; h++) { m1[p][h] = ZERO2; s1[p][h] = ZERO2; }
        m2[p] = ZERO2; s2[p] = ZERO2;
    }

    float* outp = out + b0;

#pragma unroll 4
    for (int t = 0; t < T_STEPS; t++) {
        float so[2][2];  // output spikes for the 4 lanes this step
#pragma unroll
        for (int p = 0; p < 2; p++) {
#pragma unroll
            for (int h = 0; h < 4; h++) {
                // m = beta*m + cur  (packed fma, bit-identical halves)
                u64 m = ffma2(BETA2, m1[p][h], cur[p][h]);
                // m -= s_prev : sub.rn == fma(s,-1,m) value-identical
                m = fsub2(m, s1[p][h]);
                m1[p][h] = m;
                float lo, hi; unpack2(m, lo, hi);
                s1[p][h] = pack2(fset_gt(lo, 1.0f), fset_gt(hi, 1.0f));
            }
            // o = spk1 . w2 : packed mul + fma chain, same h-order & values as scalar chain
            u64 o = fmul2(s1[p][0], W2[0]);
            o = ffma2(s1[p][1], W2[1], o);
            o = ffma2(s1[p][2], W2[2], o);
            o = ffma2(s1[p][3], W2[3], o);

            u64 m = ffma2(BETA2, m2[p], o);
            m = fsub2(m, s2[p]);
            m2[p] = m;
            float lo, hi; unpack2(m, lo, hi);
            so[p][0] = fset_gt(lo, 1.0f);
            so[p][1] = fset_gt(hi, 1.0f);
            s2[p] = pack2(so[p][0], so[p][1]);
        }
        stg_cs128(outp, so[0][0], so[0][1], so[1][0], so[1][1]);
        outp += B;  // next timestep plane
    }
}

extern "C" void kernel_launch(void* const* d_in, const int* in_sizes, int n_in,
                              void* d_out, int out_size)
{
    const float* x  = (const float*)d_in[0];   // [B, 2]
    const float* w1 = (const float*)d_in[1];   // [4, 2]
    const float* w2 = (const float*)d_in[2];   // [1, 4]
    float* out      = (float*)d_out;           // [T, B, 1]

    const int B = in_sizes[0] / 2;
    const int nthreads = B / 4;                // 4 batch elems per thread
    const int block = 256;
    const int grid = (nthreads + block - 1) / block;

    xornet_snn_kernel<<<grid, block>>>((const float4*)x, w1, w2, out, B);
}